// round 4
// baseline (speedup 1.0000x reference)
#include <cuda_runtime.h>
#include <cuda_bf16.h>

#define NN 10000
#define EE 320000
#define DD 256
#define D4 64   // DD/4

// ---------------- scratch (__device__ globals) ------------------------------
__device__ float g_xw1[NN * DD];
__device__ float g_x1 [NN * DD];
__device__ float g_xw2[NN * DD];
__device__ int   g_indeg [NN];
__device__ int   g_rank  [EE];
__device__ int   g_csroff[NN + 1];
__device__ int   g_csrsrc[EE];
__device__ float g_dinv[NN];
__device__ float g_as[NN];
__device__ float g_ad[NN];
__device__ float g_va[DD];   // W2 @ att_src
__device__ float g_vd[DD];   // W2 @ att_dst

__device__ __forceinline__ float lrelu02(float x) {
    return x > 0.f ? x : 0.2f * x;
}

// ---------------- prep: zero counters + va/vd matvec ------------------------
__global__ void __launch_bounds__(256) prep_kernel(
    const float* __restrict__ W2,
    const float* __restrict__ a_s, const float* __restrict__ a_d)
{
    int i = blockIdx.x * 256 + threadIdx.x;
    if (i < NN) g_indeg[i] = 0;

    int w = threadIdx.x >> 5, l = threadIdx.x & 31;
    int row = blockIdx.x * 8 + w;
    if (row < DD) {
        float s1 = 0.f, s2 = 0.f;
        #pragma unroll
        for (int k = 0; k < 8; k++) {
            float v = W2[row * DD + l + k * 32];
            s1 += v * a_s[l + k * 32];
            s2 += v * a_d[l + k * 32];
        }
        #pragma unroll
        for (int off = 16; off; off >>= 1) {
            s1 += __shfl_down_sync(0xffffffffu, s1, off);
            s2 += __shfl_down_sync(0xffffffffu, s2, off);
        }
        if (l == 0) { g_va[row] = s1; g_vd[row] = s2; }
    }
}

// ---------------- count in-degree + within-bucket rank, 4 edges/thread ------
__global__ void count_kernel(const int* __restrict__ ei) {
    int e4 = (blockIdx.x * blockDim.x + threadIdx.x) * 4;
    if (e4 < EE) {
        int4 d = *(const int4*)(ei + EE + e4);
        int4 r;
        r.x = atomicAdd(&g_indeg[d.x], 1);
        r.y = atomicAdd(&g_indeg[d.y], 1);
        r.z = atomicAdd(&g_indeg[d.z], 1);
        r.w = atomicAdd(&g_indeg[d.w], 1);
        *(int4*)(g_rank + e4) = r;
    }
}

// ---------------- single-block exclusive scan + dinv ------------------------
__global__ void scan_kernel() {
    __shared__ int s[1024];
    __shared__ int carry_s;
    int t = threadIdx.x;
    if (t == 0) carry_s = 0;
    __syncthreads();
    for (int base = 0; base < NN; base += 1024) {
        int idx = base + t;
        int v = (idx < NN) ? g_indeg[idx] : 0;
        if (idx < NN) g_dinv[idx] = rsqrtf((float)(v + 1));  // +1 self loop
        s[t] = v;
        __syncthreads();
        #pragma unroll
        for (int off = 1; off < 1024; off <<= 1) {
            int x = (t >= off) ? s[t - off] : 0;
            __syncthreads();
            s[t] += x;
            __syncthreads();
        }
        if (idx < NN) g_csroff[idx] = carry_s + s[t] - v;
        int total = s[1023];
        __syncthreads();
        if (t == 0) carry_s += total;
        __syncthreads();
    }
    if (t == 0) g_csroff[NN] = carry_s;
}

// ---------------- scatter edges into CSR (atomic-free) ----------------------
__global__ void fill_kernel(const int* __restrict__ ei) {
    int e4 = (blockIdx.x * blockDim.x + threadIdx.x) * 4;
    if (e4 < EE) {
        int4 sv = *(const int4*)(ei + e4);
        int4 dv = *(const int4*)(ei + EE + e4);
        int4 rv = *(const int4*)(g_rank + e4);
        g_csrsrc[g_csroff[dv.x] + rv.x] = sv.x;
        g_csrsrc[g_csroff[dv.y] + rv.y] = sv.y;
        g_csrsrc[g_csroff[dv.z] + rv.z] = sv.z;
        g_csrsrc[g_csroff[dv.w] + rv.w] = sv.w;
    }
}

// ---------------- tf32 tensor-core GEMM: C[M,256] = A[M,256] @ B[256,256] ---
// 128x128 block tile, 8 warps (32x64 warp tile), 3-pass tf32 split ~ fp32.
#define GBM 128
#define GBN 128
#define KC  16
#define APAD 4
#define ASTR (GBM + APAD)   // 132
#define BSTR (GBN + APAD)   // 132

__device__ __forceinline__ unsigned f2tf(float x) {
    unsigned r;
    asm("cvt.rna.tf32.f32 %0, %1;" : "=r"(r) : "f"(x));
    return r;
}

__device__ __forceinline__ void mma_tf32(float* d, const unsigned* a, const unsigned* b) {
    asm volatile(
        "mma.sync.aligned.m16n8k8.row.col.f32.tf32.tf32.f32 "
        "{%0,%1,%2,%3}, {%4,%5,%6,%7}, {%8,%9}, {%0,%1,%2,%3};"
        : "+f"(d[0]), "+f"(d[1]), "+f"(d[2]), "+f"(d[3])
        : "r"(a[0]), "r"(a[1]), "r"(a[2]), "r"(a[3]), "r"(b[0]), "r"(b[1]));
}

__device__ __forceinline__ void gemm_tc_body(
    const float* __restrict__ A, const float* __restrict__ B,
    float* __restrict__ C, int M)
{
    __shared__ unsigned Ah[KC][ASTR], Al[KC][ASTR];
    __shared__ unsigned Bh[KC][BSTR], Bl[KC][BSTR];

    int tid  = threadIdx.x;
    int wid  = tid >> 5, lane = tid & 31;
    int wm   = wid & 3,  wn   = wid >> 2;     // 4x2 warp grid
    int row0 = blockIdx.y * GBM, col0 = blockIdx.x * GBN;
    int g = lane >> 2, c = lane & 3;

    float acc[2][8][4];
    #pragma unroll
    for (int mf = 0; mf < 2; mf++)
        #pragma unroll
        for (int nf = 0; nf < 8; nf++)
            #pragma unroll
            for (int j = 0; j < 4; j++) acc[mf][nf][j] = 0.f;

    for (int k0 = 0; k0 < DD; k0 += KC) {
        // load + split A tile: 128 rows x KC
        {
            int r  = tid >> 2;            // 0..63
            int c4 = (tid & 3) << 2;      // 0,4,8,12
            #pragma unroll
            for (int h = 0; h < 2; h++) {
                int row = row0 + r + h * 64;
                float4 v = make_float4(0.f, 0.f, 0.f, 0.f);
                if (row < M) v = *(const float4*)(A + (long)row * DD + k0 + c4);
                float vv[4] = {v.x, v.y, v.z, v.w};
                #pragma unroll
                for (int i = 0; i < 4; i++) {
                    unsigned hi = f2tf(vv[i]);
                    float lo = vv[i] - __uint_as_float(hi);
                    Ah[c4 + i][r + h * 64] = hi;
                    Al[c4 + i][r + h * 64] = f2tf(lo);
                }
            }
        }
        // load + split B tile: KC x 128
        {
            int r  = tid >> 4;            // 0..15
            int c4 = (tid & 15) << 2;     // 0..60
            #pragma unroll
            for (int h = 0; h < 2; h++) {
                int cc = c4 + h * 64;
                float4 v = *(const float4*)(B + (long)(k0 + r) * DD + col0 + cc);
                float vv[4] = {v.x, v.y, v.z, v.w};
                #pragma unroll
                for (int i = 0; i < 4; i++) {
                    unsigned hi = f2tf(vv[i]);
                    float lo = vv[i] - __uint_as_float(hi);
                    Bh[r][cc + i] = hi;
                    Bl[r][cc + i] = f2tf(lo);
                }
            }
        }
        __syncthreads();

        #pragma unroll
        for (int k8 = 0; k8 < KC / 8; k8++) {
            unsigned ah[2][4], al[2][4], bh[8][2], bl[8][2];
            #pragma unroll
            for (int mf = 0; mf < 2; mf++)
                #pragma unroll
                for (int j = 0; j < 4; j++) {
                    int rr = wm * 32 + mf * 16 + g + 8 * (j & 1);
                    int kk = k8 * 8 + c + 4 * (j >> 1);
                    ah[mf][j] = Ah[kk][rr];
                    al[mf][j] = Al[kk][rr];
                }
            #pragma unroll
            for (int nf = 0; nf < 8; nf++)
                #pragma unroll
                for (int j = 0; j < 2; j++) {
                    int kk = k8 * 8 + c + 4 * j;
                    int nn = wn * 64 + nf * 8 + g;
                    bh[nf][j] = Bh[kk][nn];
                    bl[nf][j] = Bl[kk][nn];
                }
            #pragma unroll
            for (int mf = 0; mf < 2; mf++)
                #pragma unroll
                for (int nf = 0; nf < 8; nf++) {
                    mma_tf32(acc[mf][nf], ah[mf], bh[nf]);
                    mma_tf32(acc[mf][nf], al[mf], bh[nf]);
                    mma_tf32(acc[mf][nf], ah[mf], bl[nf]);
                }
        }
        __syncthreads();
    }

    // epilogue: c-frag rows g, g+8; cols 2c, 2c+1
    #pragma unroll
    for (int mf = 0; mf < 2; mf++)
        #pragma unroll
        for (int j2 = 0; j2 < 2; j2++) {
            int gr = row0 + wm * 32 + mf * 16 + g + 8 * j2;
            if (gr < M) {
                #pragma unroll
                for (int nf = 0; nf < 8; nf++) {
                    float2 v = make_float2(acc[mf][nf][j2 * 2],
                                           acc[mf][nf][j2 * 2 + 1]);
                    *(float2*)(C + (long)gr * DD + col0 + wn * 64 + nf * 8 + c * 2) = v;
                }
            }
        }
}

__global__ void __launch_bounds__(256) gemm1_kernel(
    const float* __restrict__ A, const float* __restrict__ B) {
    gemm_tc_body(A, B, g_xw1, NN);
}
__global__ void __launch_bounds__(256) gemm2_kernel(
    const float* __restrict__ B) {
    gemm_tc_body(g_x1, B, g_xw2, NN);
}

// ---------------- GCN aggregation + fused attention dots --------------------
__global__ void __launch_bounds__(64) gcn_agg_kernel(const float* __restrict__ b1) {
    int i = blockIdx.x;
    int t = threadIdx.x;
    __shared__ int   sj[64];
    __shared__ float sw[64];
    __shared__ float rs[64], rd[64];

    float di = g_dinv[i];
    const float4* xw = (const float4*)g_xw1;
    float4 acc = xw[(long)i * D4 + t];            // self loop
    float wself = di * di;
    acc.x *= wself; acc.y *= wself; acc.z *= wself; acc.w *= wself;

    int beg = g_csroff[i], end = g_csroff[i + 1];
    for (int base = beg; base < end; base += 64) {
        int n = end - base; if (n > 64) n = 64;
        if (t < n) {
            int j = g_csrsrc[base + t];
            sj[t] = j;
            sw[t] = di * g_dinv[j];
        }
        __syncthreads();
        #pragma unroll 4
        for (int k = 0; k < n; k++) {
            float4 v = xw[(long)sj[k] * D4 + t];
            float w = sw[k];
            acc.x += v.x * w; acc.y += v.y * w;
            acc.z += v.z * w; acc.w += v.w * w;
        }
        __syncthreads();
    }
    float4 bb = ((const float4*)b1)[t];
    acc.x = fmaxf(acc.x + bb.x, 0.f);
    acc.y = fmaxf(acc.y + bb.y, 0.f);
    acc.z = fmaxf(acc.z + bb.z, 0.f);
    acc.w = fmaxf(acc.w + bb.w, 0.f);
    ((float4*)g_x1)[(long)i * D4 + t] = acc;

    // fused attention dots: as_i = x1_i . va, ad_i = x1_i . vd
    float4 va = ((const float4*)g_va)[t];
    float4 vd = ((const float4*)g_vd)[t];
    float ds = acc.x * va.x + acc.y * va.y + acc.z * va.z + acc.w * va.w;
    float dd = acc.x * vd.x + acc.y * vd.y + acc.z * vd.z + acc.w * vd.w;
    rs[t] = ds; rd[t] = dd;
    __syncthreads();
    #pragma unroll
    for (int off = 32; off; off >>= 1) {
        if (t < off) { rs[t] += rs[t + off]; rd[t] += rd[t + off]; }
        __syncthreads();
    }
    if (t == 0) { g_as[i] = rs[0]; g_ad[i] = rd[0]; }
}

// ---------------- GAT aggregation: one block (64 thr) per dst node ----------
__global__ void __launch_bounds__(64) gat_agg_kernel(const float* __restrict__ b2,
                                                     float* __restrict__ out) {
    int i = blockIdx.x;
    int t = threadIdx.x;
    __shared__ float red[64];
    __shared__ int   sj[64];
    __shared__ float sw[64];

    float adi = g_ad[i];
    int beg = g_csroff[i], end = g_csroff[i + 1];
    float e_self = lrelu02(g_as[i] + adi);

    // pass 1a: max
    float lm = e_self;
    for (int e = beg + t; e < end; e += 64) {
        int j = g_csrsrc[e];
        lm = fmaxf(lm, lrelu02(g_as[j] + adi));
    }
    red[t] = lm; __syncthreads();
    #pragma unroll
    for (int off = 32; off; off >>= 1) {
        if (t < off) red[t] = fmaxf(red[t], red[t + off]);
        __syncthreads();
    }
    float m = red[0];
    __syncthreads();

    // pass 1b: sum of exp
    float ls = 0.f;
    for (int e = beg + t; e < end; e += 64) {
        int j = g_csrsrc[e];
        ls += __expf(lrelu02(g_as[j] + adi) - m);
    }
    red[t] = ls; __syncthreads();
    #pragma unroll
    for (int off = 32; off; off >>= 1) {
        if (t < off) red[t] += red[t + off];
        __syncthreads();
    }
    float ssum = red[0] + __expf(e_self - m);
    float inv = 1.f / (ssum + 1e-16f);
    __syncthreads();

    // pass 2: weighted aggregation
    const float4* xw = (const float4*)g_xw2;
    float4 acc = xw[(long)i * D4 + t];
    float aself = __expf(e_self - m) * inv;
    acc.x *= aself; acc.y *= aself; acc.z *= aself; acc.w *= aself;

    for (int base = beg; base < end; base += 64) {
        int n = end - base; if (n > 64) n = 64;
        if (t < n) {
            int j = g_csrsrc[base + t];
            sj[t] = j;
            sw[t] = __expf(lrelu02(g_as[j] + adi) - m) * inv;
        }
        __syncthreads();
        #pragma unroll 4
        for (int k = 0; k < n; k++) {
            float4 v = xw[(long)sj[k] * D4 + t];
            float w = sw[k];
            acc.x += v.x * w; acc.y += v.y * w;
            acc.z += v.z * w; acc.w += v.w * w;
        }
        __syncthreads();
    }
    float4 bb = ((const float4*)b2)[t];
    acc.x = fmaxf(acc.x + bb.x, 0.f);
    acc.y = fmaxf(acc.y + bb.y, 0.f);
    acc.z = fmaxf(acc.z + bb.z, 0.f);
    acc.w = fmaxf(acc.w + bb.w, 0.f);
    ((float4*)out)[(long)i * D4 + t] = acc;
}

// ---------------- launch ----------------------------------------------------
extern "C" void kernel_launch(void* const* d_in, const int* in_sizes, int n_in,
                              void* d_out, int out_size) {
    const float* event_emb = (const float*)d_in[0];
    const int*   edge_idx  = (const int*)  d_in[1];
    const float* W1        = (const float*)d_in[2];
    const float* b1        = (const float*)d_in[3];
    const float* W2        = (const float*)d_in[4];
    const float* att_src   = (const float*)d_in[5];
    const float* att_dst   = (const float*)d_in[6];
    const float* b2        = (const float*)d_in[7];
    float* out = (float*)d_out;

    // CSR build (by destination) + va/vd precompute
    prep_kernel<<<40, 256>>>(W2, att_src, att_dst);
    count_kernel<<<(EE / 4 + 255) / 256, 256>>>(edge_idx);
    scan_kernel<<<1, 1024>>>();
    fill_kernel<<<(EE / 4 + 255) / 256, 256>>>(edge_idx);

    dim3 ggrid(DD / GBN, (NN + GBM - 1) / GBM);   // (2, 79)
    // layer 1: GCN
    gemm1_kernel<<<ggrid, 256>>>(event_emb, W1);
    gcn_agg_kernel<<<NN, 64>>>(b1);
    // layer 2: GAT
    gemm2_kernel<<<ggrid, 256>>>(W2);
    gat_agg_kernel<<<NN, 64>>>(b2, out);
}

// round 6
// speedup vs baseline: 1.4923x; 1.4923x over previous
#include <cuda_runtime.h>
#include <cuda_bf16.h>

#define NN 10000
#define EE 320000
#define DD 256
#define D4 64   // DD/4

// ---------------- scratch (__device__ globals) ------------------------------
__device__ float g_xw1[NN * DD];
__device__ float g_x1 [NN * DD];
__device__ float g_xw2[NN * DD];
__device__ int   g_indeg [NN];
__device__ int   g_rank  [EE];
__device__ int   g_csroff[NN + 1];
__device__ int   g_csrsrc[EE];
__device__ float g_dinv[NN];
__device__ float g_as[NN];
__device__ float g_ad[NN];
__device__ float g_va[DD];   // W2 @ att_src
__device__ float g_vd[DD];   // W2 @ att_dst

__device__ __forceinline__ float lrelu02(float x) {
    return x > 0.f ? x : 0.2f * x;
}

// ---------------- prep: zero counters + va/vd matvec ------------------------
__global__ void __launch_bounds__(256) prep_kernel(
    const float* __restrict__ W2,
    const float* __restrict__ a_s, const float* __restrict__ a_d)
{
    int i = blockIdx.x * 256 + threadIdx.x;
    if (i < NN) g_indeg[i] = 0;

    int w = threadIdx.x >> 5, l = threadIdx.x & 31;
    int row = blockIdx.x * 8 + w;
    if (row < DD) {
        float s1 = 0.f, s2 = 0.f;
        #pragma unroll
        for (int k = 0; k < 8; k++) {
            float v = W2[row * DD + l + k * 32];
            s1 += v * a_s[l + k * 32];
            s2 += v * a_d[l + k * 32];
        }
        #pragma unroll
        for (int off = 16; off; off >>= 1) {
            s1 += __shfl_down_sync(0xffffffffu, s1, off);
            s2 += __shfl_down_sync(0xffffffffu, s2, off);
        }
        if (l == 0) { g_va[row] = s1; g_vd[row] = s2; }
    }
}

// ---------------- count in-degree + within-bucket rank, 4 edges/thread ------
__global__ void count_kernel(const int* __restrict__ ei) {
    int e4 = (blockIdx.x * blockDim.x + threadIdx.x) * 4;
    if (e4 < EE) {
        int4 d = *(const int4*)(ei + EE + e4);
        int4 r;
        r.x = atomicAdd(&g_indeg[d.x], 1);
        r.y = atomicAdd(&g_indeg[d.y], 1);
        r.z = atomicAdd(&g_indeg[d.z], 1);
        r.w = atomicAdd(&g_indeg[d.w], 1);
        *(int4*)(g_rank + e4) = r;
    }
}

// ---------------- one-pass warp-shuffle exclusive scan + dinv ---------------
// 1 block x 1024 threads, 10 contiguous elements per thread.
__global__ void __launch_bounds__(1024) scan_kernel() {
    __shared__ int wsum[32];
    int t = threadIdx.x;
    int lane = t & 31, w = t >> 5;
    int base = t * 10;

    int v[10]; int s = 0;
    #pragma unroll
    for (int u = 0; u < 10; u++) {
        int idx = base + u;
        v[u] = (idx < NN) ? g_indeg[idx] : 0;
        s += v[u];
    }
    // warp inclusive scan of per-thread sums
    int ps = s;
    #pragma unroll
    for (int off = 1; off < 32; off <<= 1) {
        int x = __shfl_up_sync(0xffffffffu, ps, off);
        if (lane >= off) ps += x;
    }
    if (lane == 31) wsum[w] = ps;
    __syncthreads();
    if (w == 0) {
        int x = wsum[lane];
        #pragma unroll
        for (int off = 1; off < 32; off <<= 1) {
            int y = __shfl_up_sync(0xffffffffu, x, off);
            if (lane >= off) x += y;
        }
        wsum[lane] = x;
    }
    __syncthreads();
    int excl = ps - s + (w > 0 ? wsum[w - 1] : 0);

    int run = excl;
    #pragma unroll
    for (int u = 0; u < 10; u++) {
        int idx = base + u;
        if (idx < NN) {
            g_csroff[idx] = run;
            g_dinv[idx] = rsqrtf((float)(v[u] + 1));  // +1 self loop
            run += v[u];
        }
    }
    if (t == 1023) g_csroff[NN] = run;   // grand total
}

// ---------------- scatter edges into CSR (atomic-free) ----------------------
__global__ void fill_kernel(const int* __restrict__ ei) {
    int e4 = (blockIdx.x * blockDim.x + threadIdx.x) * 4;
    if (e4 < EE) {
        int4 sv = *(const int4*)(ei + e4);
        int4 dv = *(const int4*)(ei + EE + e4);
        int4 rv = *(const int4*)(g_rank + e4);
        g_csrsrc[g_csroff[dv.x] + rv.x] = sv.x;
        g_csrsrc[g_csroff[dv.y] + rv.y] = sv.y;
        g_csrsrc[g_csroff[dv.z] + rv.z] = sv.z;
        g_csrsrc[g_csroff[dv.w] + rv.w] = sv.w;
    }
}

// ---------------- tf32 tensor-core GEMM (single-pass, double-buffered) ------
// C[M,256] = A[M,256] @ B[256,256]; 128x128 block tile, 8 warps (32x64 each).
#define GBM 128
#define GBN 128
#define KC  16
#define ASTR 132

__device__ __forceinline__ unsigned f2tf(float x) {
    unsigned r;
    asm("cvt.rna.tf32.f32 %0, %1;" : "=r"(r) : "f"(x));
    return r;
}

__device__ __forceinline__ void mma_tf32(float* d, const unsigned* a, const unsigned* b) {
    asm volatile(
        "mma.sync.aligned.m16n8k8.row.col.f32.tf32.tf32.f32 "
        "{%0,%1,%2,%3}, {%4,%5,%6,%7}, {%8,%9}, {%0,%1,%2,%3};"
        : "+f"(d[0]), "+f"(d[1]), "+f"(d[2]), "+f"(d[3])
        : "r"(a[0]), "r"(a[1]), "r"(a[2]), "r"(a[3]), "r"(b[0]), "r"(b[1]));
}

__device__ __forceinline__ float4 ldA4(const float* __restrict__ A,
                                       int r, int c, int M) {
    if (r < M) return *(const float4*)(A + (long)r * DD + c);
    return make_float4(0.f, 0.f, 0.f, 0.f);
}

__device__ __forceinline__ void gemm_tc_body(
    const float* __restrict__ A, const float* __restrict__ B,
    float* __restrict__ C, int M)
{
    __shared__ unsigned Ah[2][KC][ASTR];   // [k][m], m contiguous
    __shared__ unsigned Bh[2][KC][ASTR];   // [k][n], n contiguous

    int tid  = threadIdx.x;
    int wid  = tid >> 5, lane = tid & 31;
    int wm   = wid & 3,  wn   = wid >> 2;     // 4x2 warp grid
    int row0 = blockIdx.y * GBM, col0 = blockIdx.x * GBN;
    int g = lane >> 2, c = lane & 3;

    // loader coords
    int ar = tid >> 2;            // 0..63
    int ac = (tid & 3) << 2;      // 0,4,8,12
    int br = tid >> 4;            // 0..15
    int bc = (tid & 15) << 2;     // 0..60

    float acc[2][8][4];
    #pragma unroll
    for (int mf = 0; mf < 2; mf++)
        #pragma unroll
        for (int nf = 0; nf < 8; nf++)
            #pragma unroll
            for (int j = 0; j < 4; j++) acc[mf][nf][j] = 0.f;

    // prologue: tile 0 -> buf 0
    {
        float4 a0 = ldA4(A, row0 + ar,      ac, M);
        float4 a1 = ldA4(A, row0 + ar + 64, ac, M);
        float4 b0 = *(const float4*)(B + (long)br * DD + col0 + bc);
        float4 b1 = *(const float4*)(B + (long)br * DD + col0 + bc + 64);
        float av0[4] = {a0.x, a0.y, a0.z, a0.w};
        float av1[4] = {a1.x, a1.y, a1.z, a1.w};
        #pragma unroll
        for (int i = 0; i < 4; i++) {
            Ah[0][ac + i][ar]      = f2tf(av0[i]);
            Ah[0][ac + i][ar + 64] = f2tf(av1[i]);
        }
        uint4 p0 = make_uint4(f2tf(b0.x), f2tf(b0.y), f2tf(b0.z), f2tf(b0.w));
        uint4 p1 = make_uint4(f2tf(b1.x), f2tf(b1.y), f2tf(b1.z), f2tf(b1.w));
        *(uint4*)&Bh[0][br][bc]      = p0;
        *(uint4*)&Bh[0][br][bc + 64] = p1;
    }
    __syncthreads();

    #pragma unroll 1
    for (int kt = 0; kt < DD / KC; kt++) {
        int buf = kt & 1;
        float4 na0, na1, nb0, nb1;
        if (kt < DD / KC - 1) {
            int k0 = (kt + 1) * KC;
            na0 = ldA4(A, row0 + ar,      k0 + ac, M);
            na1 = ldA4(A, row0 + ar + 64, k0 + ac, M);
            nb0 = *(const float4*)(B + (long)(k0 + br) * DD + col0 + bc);
            nb1 = *(const float4*)(B + (long)(k0 + br) * DD + col0 + bc + 64);
        }
        #pragma unroll
        for (int k8 = 0; k8 < KC / 8; k8++) {
            unsigned ah[2][4], bh[8][2];
            #pragma unroll
            for (int mf = 0; mf < 2; mf++)
                #pragma unroll
                for (int j = 0; j < 4; j++) {
                    int rr = wm * 32 + mf * 16 + g + 8 * (j & 1);
                    int kk = k8 * 8 + c + 4 * (j >> 1);
                    ah[mf][j] = Ah[buf][kk][rr];
                }
            #pragma unroll
            for (int nf = 0; nf < 8; nf++)
                #pragma unroll
                for (int j = 0; j < 2; j++) {
                    int kk = k8 * 8 + c + 4 * j;
                    int nn = wn * 64 + nf * 8 + g;
                    bh[nf][j] = Bh[buf][kk][nn];
                }
            #pragma unroll
            for (int mf = 0; mf < 2; mf++)
                #pragma unroll
                for (int nf = 0; nf < 8; nf++)
                    mma_tf32(acc[mf][nf], ah[mf], bh[nf]);
        }
        if (kt < DD / KC - 1) {
            int nb = buf ^ 1;
            float av0[4] = {na0.x, na0.y, na0.z, na0.w};
            float av1[4] = {na1.x, na1.y, na1.z, na1.w};
            #pragma unroll
            for (int i = 0; i < 4; i++) {
                Ah[nb][ac + i][ar]      = f2tf(av0[i]);
                Ah[nb][ac + i][ar + 64] = f2tf(av1[i]);
            }
            uint4 p0 = make_uint4(f2tf(nb0.x), f2tf(nb0.y), f2tf(nb0.z), f2tf(nb0.w));
            uint4 p1 = make_uint4(f2tf(nb1.x), f2tf(nb1.y), f2tf(nb1.z), f2tf(nb1.w));
            *(uint4*)&Bh[nb][br][bc]      = p0;
            *(uint4*)&Bh[nb][br][bc + 64] = p1;
            __syncthreads();
        }
    }

    // epilogue
    #pragma unroll
    for (int mf = 0; mf < 2; mf++)
        #pragma unroll
        for (int j2 = 0; j2 < 2; j2++) {
            int gr = row0 + wm * 32 + mf * 16 + g + 8 * j2;
            if (gr < M) {
                #pragma unroll
                for (int nf = 0; nf < 8; nf++) {
                    float2 v = make_float2(acc[mf][nf][j2 * 2],
                                           acc[mf][nf][j2 * 2 + 1]);
                    *(float2*)(C + (long)gr * DD + col0 + wn * 64 + nf * 8 + c * 2) = v;
                }
            }
        }
}

__global__ void __launch_bounds__(256) gemm1_kernel(
    const float* __restrict__ A, const float* __restrict__ B) {
    gemm_tc_body(A, B, g_xw1, NN);
}
__global__ void __launch_bounds__(256) gemm2_kernel(
    const float* __restrict__ B) {
    gemm_tc_body(g_x1, B, g_xw2, NN);
}

// ---------------- GCN aggregation + fused attention dots --------------------
__global__ void __launch_bounds__(64) gcn_agg_kernel(const float* __restrict__ b1) {
    int i = blockIdx.x;
    int t = threadIdx.x;
    __shared__ int   sj[64];
    __shared__ float sw[64];
    __shared__ float rs[64], rd[64];

    float di = g_dinv[i];
    const float4* xw = (const float4*)g_xw1;
    float4 acc = xw[(long)i * D4 + t];            // self loop
    float wself = di * di;
    acc.x *= wself; acc.y *= wself; acc.z *= wself; acc.w *= wself;

    int beg = g_csroff[i], end = g_csroff[i + 1];
    for (int base = beg; base < end; base += 64) {
        int n = end - base; if (n > 64) n = 64;
        if (t < n) {
            int j = g_csrsrc[base + t];
            sj[t] = j;
            sw[t] = di * g_dinv[j];
        }
        __syncthreads();
        #pragma unroll 4
        for (int k = 0; k < n; k++) {
            float4 v = xw[(long)sj[k] * D4 + t];
            float w = sw[k];
            acc.x += v.x * w; acc.y += v.y * w;
            acc.z += v.z * w; acc.w += v.w * w;
        }
        __syncthreads();
    }
    float4 bb = ((const float4*)b1)[t];
    acc.x = fmaxf(acc.x + bb.x, 0.f);
    acc.y = fmaxf(acc.y + bb.y, 0.f);
    acc.z = fmaxf(acc.z + bb.z, 0.f);
    acc.w = fmaxf(acc.w + bb.w, 0.f);
    ((float4*)g_x1)[(long)i * D4 + t] = acc;

    // fused attention dots: as_i = x1_i . va, ad_i = x1_i . vd
    float4 va = ((const float4*)g_va)[t];
    float4 vd = ((const float4*)g_vd)[t];
    float ds = acc.x * va.x + acc.y * va.y + acc.z * va.z + acc.w * va.w;
    float dd = acc.x * vd.x + acc.y * vd.y + acc.z * vd.z + acc.w * vd.w;
    rs[t] = ds; rd[t] = dd;
    __syncthreads();
    #pragma unroll
    for (int off = 32; off; off >>= 1) {
        if (t < off) { rs[t] += rs[t + off]; rd[t] += rd[t + off]; }
        __syncthreads();
    }
    if (t == 0) { g_as[i] = rs[0]; g_ad[i] = rd[0]; }
}

// ---------------- GAT aggregation: online softmax + gather ------------------
__global__ void __launch_bounds__(64) gat_agg_kernel(const float* __restrict__ b2,
                                                     float* __restrict__ out) {
    int i = blockIdx.x;
    int t = threadIdx.x;
    __shared__ float red_m[64], red_s[64];
    __shared__ int   sj[64];
    __shared__ float sw[64];

    float adi = g_ad[i];
    int beg = g_csroff[i], end = g_csroff[i + 1];
    float e_self = lrelu02(g_as[i] + adi);

    // single online-softmax pass: per-thread running (m, s)
    float lm = -1e30f, ls = 0.f;
    for (int e = beg + t; e < end; e += 64) {
        int j = g_csrsrc[e];
        float ev = lrelu02(g_as[j] + adi);
        if (ev > lm) { ls = ls * __expf(lm - ev) + 1.f; lm = ev; }
        else         { ls += __expf(ev - lm); }
    }
    red_m[t] = lm; red_s[t] = ls;
    __syncthreads();
    #pragma unroll
    for (int off = 32; off; off >>= 1) {
        if (t < off) {
            float m1 = red_m[t], m2 = red_m[t + off];
            float M = fmaxf(m1, m2);
            red_s[t] = red_s[t] * __expf(m1 - M) + red_s[t + off] * __expf(m2 - M);
            red_m[t] = M;
        }
        __syncthreads();
    }
    float m, ssum;
    {   // merge self term (exactly once)
        float m1 = red_m[0];
        m = fmaxf(m1, e_self);
        ssum = red_s[0] * __expf(m1 - m) + __expf(e_self - m);
    }
    float inv = 1.f / (ssum + 1e-16f);
    __syncthreads();

    // weighted aggregation
    const float4* xw = (const float4*)g_xw2;
    float4 acc = xw[(long)i * D4 + t];
    float aself = __expf(e_self - m) * inv;
    acc.x *= aself; acc.y *= aself; acc.z *= aself; acc.w *= aself;

    for (int base = beg; base < end; base += 64) {
        int n = end - base; if (n > 64) n = 64;
        if (t < n) {
            int j = g_csrsrc[base + t];
            sj[t] = j;
            sw[t] = __expf(lrelu02(g_as[j] + adi) - m) * inv;
        }
        __syncthreads();
        #pragma unroll 4
        for (int k = 0; k < n; k++) {
            float4 v = xw[(long)sj[k] * D4 + t];
            float w = sw[k];
            acc.x += v.x * w; acc.y += v.y * w;
            acc.z += v.z * w; acc.w += v.w * w;
        }
        __syncthreads();
    }
    float4 bb = ((const float4*)b2)[t];
    acc.x = fmaxf(acc.x + bb.x, 0.f);
    acc.y = fmaxf(acc.y + bb.y, 0.f);
    acc.z = fmaxf(acc.z + bb.z, 0.f);
    acc.w = fmaxf(acc.w + bb.w, 0.f);
    ((float4*)out)[(long)i * D4 + t] = acc;
}

// ---------------- launch ----------------------------------------------------
extern "C" void kernel_launch(void* const* d_in, const int* in_sizes, int n_in,
                              void* d_out, int out_size) {
    const float* event_emb = (const float*)d_in[0];
    const int*   edge_idx  = (const int*)  d_in[1];
    const float* W1        = (const float*)d_in[2];
    const float* b1        = (const float*)d_in[3];
    const float* W2        = (const float*)d_in[4];
    const float* att_src   = (const float*)d_in[5];
    const float* att_dst   = (const float*)d_in[6];
    const float* b2        = (const float*)d_in[7];
    float* out = (float*)d_out;

    // CSR build (by destination) + va/vd precompute
    prep_kernel<<<40, 256>>>(W2, att_src, att_dst);
    count_kernel<<<(EE / 4 + 255) / 256, 256>>>(edge_idx);
    scan_kernel<<<1, 1024>>>();
    fill_kernel<<<(EE / 4 + 255) / 256, 256>>>(edge_idx);

    dim3 ggrid(DD / GBN, (NN + GBM - 1) / GBM);   // (2, 79)
    // layer 1: GCN
    gemm1_kernel<<<ggrid, 256>>>(event_emb, W1);
    gcn_agg_kernel<<<NN, 64>>>(b1);
    // layer 2: GAT
    gemm2_kernel<<<ggrid, 256>>>(W2);
    gat_agg_kernel<<<NN, 64>>>(b2, out);
}

// round 11
// speedup vs baseline: 1.5590x; 1.0447x over previous
#include <cuda_runtime.h>
#include <cuda_bf16.h>

#define NN 10000
#define EE 320000
#define DD 256
#define D4 64   // DD/4

// ---------------- scratch (__device__ globals) ------------------------------
__device__ float g_xw1[NN * DD];
__device__ float g_x1 [NN * DD];
__device__ float g_xw2[NN * DD];
__device__ int   g_indeg [NN];
__device__ int   g_rank  [EE];
__device__ int   g_csroff[NN + 1];
__device__ int   g_csrsrc[EE];
__device__ float g_dinv[NN];
__device__ float g_as[NN];
__device__ float g_ad[NN];
__device__ float g_va[DD];   // W2 @ att_src
__device__ float g_vd[DD];   // W2 @ att_dst

__device__ __forceinline__ float lrelu02(float x) {
    return x > 0.f ? x : 0.2f * x;
}

// ---------------- prep: zero counters + va/vd matvec ------------------------
__global__ void __launch_bounds__(256) prep_kernel(
    const float* __restrict__ W2,
    const float* __restrict__ a_s, const float* __restrict__ a_d)
{
    int i = blockIdx.x * 256 + threadIdx.x;
    if (i < NN) g_indeg[i] = 0;

    int w = threadIdx.x >> 5, l = threadIdx.x & 31;
    int row = blockIdx.x * 8 + w;
    if (row < DD) {
        float s1 = 0.f, s2 = 0.f;
        #pragma unroll
        for (int k = 0; k < 8; k++) {
            float v = W2[row * DD + l + k * 32];
            s1 += v * a_s[l + k * 32];
            s2 += v * a_d[l + k * 32];
        }
        #pragma unroll
        for (int off = 16; off; off >>= 1) {
            s1 += __shfl_down_sync(0xffffffffu, s1, off);
            s2 += __shfl_down_sync(0xffffffffu, s2, off);
        }
        if (l == 0) { g_va[row] = s1; g_vd[row] = s2; }
    }
}

// ---------------- count in-degree + rank, 8 edges/thread --------------------
__global__ void count_kernel(const int* __restrict__ ei) {
    int e8 = (blockIdx.x * blockDim.x + threadIdx.x) * 8;
    if (e8 < EE) {
        int4 d0 = *(const int4*)(ei + EE + e8);
        int4 d1 = *(const int4*)(ei + EE + e8 + 4);
        int4 r0, r1;
        r0.x = atomicAdd(&g_indeg[d0.x], 1);
        r0.y = atomicAdd(&g_indeg[d0.y], 1);
        r0.z = atomicAdd(&g_indeg[d0.z], 1);
        r0.w = atomicAdd(&g_indeg[d0.w], 1);
        r1.x = atomicAdd(&g_indeg[d1.x], 1);
        r1.y = atomicAdd(&g_indeg[d1.y], 1);
        r1.z = atomicAdd(&g_indeg[d1.z], 1);
        r1.w = atomicAdd(&g_indeg[d1.w], 1);
        *(int4*)(g_rank + e8)     = r0;
        *(int4*)(g_rank + e8 + 4) = r1;
    }
}

// ---------------- one-pass warp-shuffle exclusive scan + dinv ---------------
__global__ void __launch_bounds__(1024) scan_kernel() {
    __shared__ int wsum[32];
    int t = threadIdx.x;
    int lane = t & 31, w = t >> 5;
    int base = t * 10;

    int v[10]; int s = 0;
    #pragma unroll
    for (int u = 0; u < 10; u++) {
        int idx = base + u;
        v[u] = (idx < NN) ? g_indeg[idx] : 0;
        s += v[u];
    }
    int ps = s;
    #pragma unroll
    for (int off = 1; off < 32; off <<= 1) {
        int x = __shfl_up_sync(0xffffffffu, ps, off);
        if (lane >= off) ps += x;
    }
    if (lane == 31) wsum[w] = ps;
    __syncthreads();
    if (w == 0) {
        int x = wsum[lane];
        #pragma unroll
        for (int off = 1; off < 32; off <<= 1) {
            int y = __shfl_up_sync(0xffffffffu, x, off);
            if (lane >= off) x += y;
        }
        wsum[lane] = x;
    }
    __syncthreads();
    int excl = ps - s + (w > 0 ? wsum[w - 1] : 0);

    int run = excl;
    #pragma unroll
    for (int u = 0; u < 10; u++) {
        int idx = base + u;
        if (idx < NN) {
            g_csroff[idx] = run;
            g_dinv[idx] = rsqrtf((float)(v[u] + 1));  // +1 self loop
            run += v[u];
        }
    }
    if (t == 1023) g_csroff[NN] = run;
}

// ---------------- scatter edges into CSR (atomic-free), 8/thread ------------
__global__ void fill_kernel(const int* __restrict__ ei) {
    int e8 = (blockIdx.x * blockDim.x + threadIdx.x) * 8;
    if (e8 < EE) {
        int4 sv0 = *(const int4*)(ei + e8);
        int4 sv1 = *(const int4*)(ei + e8 + 4);
        int4 dv0 = *(const int4*)(ei + EE + e8);
        int4 dv1 = *(const int4*)(ei + EE + e8 + 4);
        int4 rv0 = *(const int4*)(g_rank + e8);
        int4 rv1 = *(const int4*)(g_rank + e8 + 4);
        g_csrsrc[g_csroff[dv0.x] + rv0.x] = sv0.x;
        g_csrsrc[g_csroff[dv0.y] + rv0.y] = sv0.y;
        g_csrsrc[g_csroff[dv0.z] + rv0.z] = sv0.z;
        g_csrsrc[g_csroff[dv0.w] + rv0.w] = sv0.w;
        g_csrsrc[g_csroff[dv1.x] + rv1.x] = sv1.x;
        g_csrsrc[g_csroff[dv1.y] + rv1.y] = sv1.y;
        g_csrsrc[g_csroff[dv1.z] + rv1.z] = sv1.z;
        g_csrsrc[g_csroff[dv1.w] + rv1.w] = sv1.w;
    }
}

// ---------------- tf32 tensor-core GEMM (single-pass, double-buffered) ------
#define GBM 128
#define GBN 128
#define KC  16
#define ASTR 132

__device__ __forceinline__ unsigned f2tf(float x) {
    unsigned r;
    asm("cvt.rna.tf32.f32 %0, %1;" : "=r"(r) : "f"(x));
    return r;
}

__device__ __forceinline__ void mma_tf32(float* d, const unsigned* a, const unsigned* b) {
    asm volatile(
        "mma.sync.aligned.m16n8k8.row.col.f32.tf32.tf32.f32 "
        "{%0,%1,%2,%3}, {%4,%5,%6,%7}, {%8,%9}, {%0,%1,%2,%3};"
        : "+f"(d[0]), "+f"(d[1]), "+f"(d[2]), "+f"(d[3])
        : "r"(a[0]), "r"(a[1]), "r"(a[2]), "r"(a[3]), "r"(b[0]), "r"(b[1]));
}

__device__ __forceinline__ float4 ldA4(const float* __restrict__ A,
                                       int r, int c, int M) {
    if (r < M) return *(const float4*)(A + (long)r * DD + c);
    return make_float4(0.f, 0.f, 0.f, 0.f);
}

__device__ __forceinline__ void gemm_tc_body(
    const float* __restrict__ A, const float* __restrict__ B,
    float* __restrict__ C, int M)
{
    __shared__ unsigned Ah[2][KC][ASTR];
    __shared__ unsigned Bh[2][KC][ASTR];

    int tid  = threadIdx.x;
    int wid  = tid >> 5, lane = tid & 31;
    int wm   = wid & 3,  wn   = wid >> 2;
    int row0 = blockIdx.y * GBM, col0 = blockIdx.x * GBN;
    int g = lane >> 2, c = lane & 3;

    int ar = tid >> 2;
    int ac = (tid & 3) << 2;
    int br = tid >> 4;
    int bc = (tid & 15) << 2;

    float acc[2][8][4];
    #pragma unroll
    for (int mf = 0; mf < 2; mf++)
        #pragma unroll
        for (int nf = 0; nf < 8; nf++)
            #pragma unroll
            for (int j = 0; j < 4; j++) acc[mf][nf][j] = 0.f;

    {
        float4 a0 = ldA4(A, row0 + ar,      ac, M);
        float4 a1 = ldA4(A, row0 + ar + 64, ac, M);
        float4 b0 = *(const float4*)(B + (long)br * DD + col0 + bc);
        float4 b1 = *(const float4*)(B + (long)br * DD + col0 + bc + 64);
        float av0[4] = {a0.x, a0.y, a0.z, a0.w};
        float av1[4] = {a1.x, a1.y, a1.z, a1.w};
        #pragma unroll
        for (int i = 0; i < 4; i++) {
            Ah[0][ac + i][ar]      = f2tf(av0[i]);
            Ah[0][ac + i][ar + 64] = f2tf(av1[i]);
        }
        uint4 p0 = make_uint4(f2tf(b0.x), f2tf(b0.y), f2tf(b0.z), f2tf(b0.w));
        uint4 p1 = make_uint4(f2tf(b1.x), f2tf(b1.y), f2tf(b1.z), f2tf(b1.w));
        *(uint4*)&Bh[0][br][bc]      = p0;
        *(uint4*)&Bh[0][br][bc + 64] = p1;
    }
    __syncthreads();

    #pragma unroll 1
    for (int kt = 0; kt < DD / KC; kt++) {
        int buf = kt & 1;
        float4 na0, na1, nb0, nb1;
        if (kt < DD / KC - 1) {
            int k0 = (kt + 1) * KC;
            na0 = ldA4(A, row0 + ar,      k0 + ac, M);
            na1 = ldA4(A, row0 + ar + 64, k0 + ac, M);
            nb0 = *(const float4*)(B + (long)(k0 + br) * DD + col0 + bc);
            nb1 = *(const float4*)(B + (long)(k0 + br) * DD + col0 + bc + 64);
        }
        #pragma unroll
        for (int k8 = 0; k8 < KC / 8; k8++) {
            unsigned ah[2][4], bh[8][2];
            #pragma unroll
            for (int mf = 0; mf < 2; mf++)
                #pragma unroll
                for (int j = 0; j < 4; j++) {
                    int rr = wm * 32 + mf * 16 + g + 8 * (j & 1);
                    int kk = k8 * 8 + c + 4 * (j >> 1);
                    ah[mf][j] = Ah[buf][kk][rr];
                }
            #pragma unroll
            for (int nf = 0; nf < 8; nf++)
                #pragma unroll
                for (int j = 0; j < 2; j++) {
                    int kk = k8 * 8 + c + 4 * j;
                    int nn = wn * 64 + nf * 8 + g;
                    bh[nf][j] = Bh[buf][kk][nn];
                }
            #pragma unroll
            for (int mf = 0; mf < 2; mf++)
                #pragma unroll
                for (int nf = 0; nf < 8; nf++)
                    mma_tf32(acc[mf][nf], ah[mf], bh[nf]);
        }
        if (kt < DD / KC - 1) {
            int nb = buf ^ 1;
            float av0[4] = {na0.x, na0.y, na0.z, na0.w};
            float av1[4] = {na1.x, na1.y, na1.z, na1.w};
            #pragma unroll
            for (int i = 0; i < 4; i++) {
                Ah[nb][ac + i][ar]      = f2tf(av0[i]);
                Ah[nb][ac + i][ar + 64] = f2tf(av1[i]);
            }
            uint4 p0 = make_uint4(f2tf(nb0.x), f2tf(nb0.y), f2tf(nb0.z), f2tf(nb0.w));
            uint4 p1 = make_uint4(f2tf(nb1.x), f2tf(nb1.y), f2tf(nb1.z), f2tf(nb1.w));
            *(uint4*)&Bh[nb][br][bc]      = p0;
            *(uint4*)&Bh[nb][br][bc + 64] = p1;
            __syncthreads();
        }
    }

    #pragma unroll
    for (int mf = 0; mf < 2; mf++)
        #pragma unroll
        for (int j2 = 0; j2 < 2; j2++) {
            int gr = row0 + wm * 32 + mf * 16 + g + 8 * j2;
            if (gr < M) {
                #pragma unroll
                for (int nf = 0; nf < 8; nf++) {
                    float2 v = make_float2(acc[mf][nf][j2 * 2],
                                           acc[mf][nf][j2 * 2 + 1]);
                    *(float2*)(C + (long)gr * DD + col0 + wn * 64 + nf * 8 + c * 2) = v;
                }
            }
        }
}

__global__ void __launch_bounds__(256) gemm1_kernel(
    const float* __restrict__ A, const float* __restrict__ B) {
    gemm_tc_body(A, B, g_xw1, NN);
}
__global__ void __launch_bounds__(256) gemm2_kernel(
    const float* __restrict__ B) {
    gemm_tc_body(g_x1, B, g_xw2, NN);
}

// ---------------- GCN aggregation + fused attention dots --------------------
__global__ void __launch_bounds__(64) gcn_agg_kernel(const float* __restrict__ b1) {
    int i = blockIdx.x;
    int t = threadIdx.x;
    int lane = t & 31, w = t >> 5;
    __shared__ int   sj[64];
    __shared__ float sw[64];
    __shared__ float pr[4];   // 2 warps x (ds, dd)

    float di = g_dinv[i];
    const float4* xw = (const float4*)g_xw1;
    float4 acc = xw[(long)i * D4 + t];            // self loop
    float wself = di * di;
    acc.x *= wself; acc.y *= wself; acc.z *= wself; acc.w *= wself;

    int beg = g_csroff[i], end = g_csroff[i + 1];
    for (int base = beg; base < end; base += 64) {
        int n = end - base; if (n > 64) n = 64;
        if (t < n) {
            int j = g_csrsrc[base + t];
            sj[t] = j;
            sw[t] = di * g_dinv[j];
        }
        __syncthreads();
        #pragma unroll 8
        for (int k = 0; k < n; k++) {
            float4 v = xw[(long)sj[k] * D4 + t];
            float ww = sw[k];
            acc.x += v.x * ww; acc.y += v.y * ww;
            acc.z += v.z * ww; acc.w += v.w * ww;
        }
        __syncthreads();
    }
    float4 bb = ((const float4*)b1)[t];
    acc.x = fmaxf(acc.x + bb.x, 0.f);
    acc.y = fmaxf(acc.y + bb.y, 0.f);
    acc.z = fmaxf(acc.z + bb.z, 0.f);
    acc.w = fmaxf(acc.w + bb.w, 0.f);
    ((float4*)g_x1)[(long)i * D4 + t] = acc;

    // fused attention dots via shfl (2 warps)
    float4 va = ((const float4*)g_va)[t];
    float4 vd = ((const float4*)g_vd)[t];
    float ds = acc.x * va.x + acc.y * va.y + acc.z * va.z + acc.w * va.w;
    float dd = acc.x * vd.x + acc.y * vd.y + acc.z * vd.z + acc.w * vd.w;
    #pragma unroll
    for (int off = 16; off; off >>= 1) {
        ds += __shfl_down_sync(0xffffffffu, ds, off);
        dd += __shfl_down_sync(0xffffffffu, dd, off);
    }
    if (lane == 0) { pr[w * 2] = ds; pr[w * 2 + 1] = dd; }
    __syncthreads();
    if (t == 0) {
        g_as[i] = pr[0] + pr[2];
        g_ad[i] = pr[1] + pr[3];
    }
}

// ---------------- GAT aggregation: online softmax + gather ------------------
__global__ void __launch_bounds__(64) gat_agg_kernel(const float* __restrict__ b2,
                                                     float* __restrict__ out) {
    int i = blockIdx.x;
    int t = threadIdx.x;
    int lane = t & 31, w = t >> 5;
    __shared__ int   sj[64];
    __shared__ float sw[64];
    __shared__ float pm[2], psum[2];

    float adi = g_ad[i];
    int beg = g_csroff[i], end = g_csroff[i + 1];
    float e_self = lrelu02(g_as[i] + adi);

    // online softmax pass: per-thread running (m, s), merged via shfl
    float lm = -1e30f, ls = 0.f;
    for (int e = beg + t; e < end; e += 64) {
        int j = g_csrsrc[e];
        float ev = lrelu02(g_as[j] + adi);
        if (ev > lm) { ls = ls * __expf(lm - ev) + 1.f; lm = ev; }
        else         { ls += __expf(ev - lm); }
    }
    #pragma unroll
    for (int off = 16; off; off >>= 1) {
        float m2 = __shfl_down_sync(0xffffffffu, lm, off);
        float s2 = __shfl_down_sync(0xffffffffu, ls, off);
        float M = fmaxf(lm, m2);
        ls = ls * __expf(lm - M) + s2 * __expf(m2 - M);
        lm = M;
    }
    if (lane == 0) { pm[w] = lm; psum[w] = ls; }
    __syncthreads();
    float m, ssum;
    {   // all threads merge the 2 warp partials + self term
        float m0 = pm[0], s0 = psum[0];
        float m1 = pm[1], s1 = psum[1];
        float M01 = fmaxf(m0, m1);
        float s01 = s0 * __expf(m0 - M01) + s1 * __expf(m1 - M01);
        m = fmaxf(M01, e_self);
        ssum = s01 * __expf(M01 - m) + __expf(e_self - m);
    }
    float inv = 1.f / (ssum + 1e-16f);
    __syncthreads();

    // weighted aggregation
    const float4* xw = (const float4*)g_xw2;
    float4 acc = xw[(long)i * D4 + t];
    float aself = __expf(e_self - m) * inv;
    acc.x *= aself; acc.y *= aself; acc.z *= aself; acc.w *= aself;

    for (int base = beg; base < end; base += 64) {
        int n = end - base; if (n > 64) n = 64;
        if (t < n) {
            int j = g_csrsrc[base + t];
            sj[t] = j;
            sw[t] = __expf(lrelu02(g_as[j] + adi) - m) * inv;
        }
        __syncthreads();
        #pragma unroll 8
        for (int k = 0; k < n; k++) {
            float4 v = xw[(long)sj[k] * D4 + t];
            float ww = sw[k];
            acc.x += v.x * ww; acc.y += v.y * ww;
            acc.z += v.z * ww; acc.w += v.w * ww;
        }
        __syncthreads();
    }
    float4 bb = ((const float4*)b2)[t];
    acc.x = fmaxf(acc.x + bb.x, 0.f);
    acc.y = fmaxf(acc.y + bb.y, 0.f);
    acc.z = fmaxf(acc.z + bb.z, 0.f);
    acc.w = fmaxf(acc.w + bb.w, 0.f);
    ((float4*)out)[(long)i * D4 + t] = acc;
}

// ---------------- launch ----------------------------------------------------
extern "C" void kernel_launch(void* const* d_in, const int* in_sizes, int n_in,
                              void* d_out, int out_size) {
    const float* event_emb = (const float*)d_in[0];
    const int*   edge_idx  = (const int*)  d_in[1];
    const float* W1        = (const float*)d_in[2];
    const float* b1        = (const float*)d_in[3];
    const float* W2        = (const float*)d_in[4];
    const float* att_src   = (const float*)d_in[5];
    const float* att_dst   = (const float*)d_in[6];
    const float* b2        = (const float*)d_in[7];
    float* out = (float*)d_out;

    prep_kernel<<<40, 256>>>(W2, att_src, att_dst);
    count_kernel<<<(EE / 8 + 255) / 256, 256>>>(edge_idx);
    scan_kernel<<<1, 1024>>>();
    fill_kernel<<<(EE / 8 + 255) / 256, 256>>>(edge_idx);

    dim3 ggrid(DD / GBN, (NN + GBM - 1) / GBM);   // (2, 79)
    gemm1_kernel<<<ggrid, 256>>>(event_emb, W1);
    gcn_agg_kernel<<<NN, 64>>>(b1);
    gemm2_kernel<<<ggrid, 256>>>(W2);
    gat_agg_kernel<<<NN, 64>>>(b2, out);
}

// round 16
// speedup vs baseline: 1.7040x; 1.0930x over previous
#include <cuda_runtime.h>
#include <cuda_fp16.h>

#define NN 10000
#define EE 320000
#define DD 256
#define D4 64    // DD/4 floats
#define DH 128   // DD/2 half2 words per row
#define DU 32    // DD/8 uint4 chunks per row

// ---------------- scratch (__device__ globals) ------------------------------
__device__ unsigned g_xw1h[NN * DH];   // x@W1 as half2 words
__device__ unsigned g_xw2h[NN * DH];   // x1@W2 as half2 words
__device__ float g_x1 [NN * DD];
__device__ int   g_indeg [NN];
__device__ int   g_rank  [EE];
__device__ int   g_csroff[NN + 1];
__device__ int   g_csrsrc[EE];
__device__ float g_dinv[NN];
__device__ float g_as[NN];
__device__ float g_ad[NN];
__device__ float g_va[DD];   // W2 @ att_src
__device__ float g_vd[DD];   // W2 @ att_dst

__device__ __forceinline__ float lrelu02(float x) {
    return x > 0.f ? x : 0.2f * x;
}

// unpack one uint4 (8 halfs) and fma into 8 fp32 accumulators
__device__ __forceinline__ void acc8(uint4 u, float ww, float* a) {
    float2 f0 = __half22float2(*(__half2*)&u.x);
    float2 f1 = __half22float2(*(__half2*)&u.y);
    float2 f2 = __half22float2(*(__half2*)&u.z);
    float2 f3 = __half22float2(*(__half2*)&u.w);
    a[0] += f0.x * ww; a[1] += f0.y * ww;
    a[2] += f1.x * ww; a[3] += f1.y * ww;
    a[4] += f2.x * ww; a[5] += f2.y * ww;
    a[6] += f3.x * ww; a[7] += f3.y * ww;
}

// ---------------- prep: zero counters + va/vd matvec ------------------------
__global__ void __launch_bounds__(256) prep_kernel(
    const float* __restrict__ W2,
    const float* __restrict__ a_s, const float* __restrict__ a_d)
{
    int i = blockIdx.x * 256 + threadIdx.x;
    if (i < NN) g_indeg[i] = 0;

    int w = threadIdx.x >> 5, l = threadIdx.x & 31;
    int row = blockIdx.x * 8 + w;
    if (row < DD) {
        float s1 = 0.f, s2 = 0.f;
        #pragma unroll
        for (int k = 0; k < 8; k++) {
            float v = W2[row * DD + l + k * 32];
            s1 += v * a_s[l + k * 32];
            s2 += v * a_d[l + k * 32];
        }
        #pragma unroll
        for (int off = 16; off; off >>= 1) {
            s1 += __shfl_down_sync(0xffffffffu, s1, off);
            s2 += __shfl_down_sync(0xffffffffu, s2, off);
        }
        if (l == 0) { g_va[row] = s1; g_vd[row] = s2; }
    }
}

// ---------------- one-pass warp-shuffle exclusive scan + dinv ---------------
__global__ void __launch_bounds__(1024) scan_kernel() {
    __shared__ int wsum[32];
    int t = threadIdx.x;
    int lane = t & 31, w = t >> 5;
    int base = t * 10;

    int v[10]; int s = 0;
    #pragma unroll
    for (int u = 0; u < 10; u++) {
        int idx = base + u;
        v[u] = (idx < NN) ? g_indeg[idx] : 0;
        s += v[u];
    }
    int ps = s;
    #pragma unroll
    for (int off = 1; off < 32; off <<= 1) {
        int x = __shfl_up_sync(0xffffffffu, ps, off);
        if (lane >= off) ps += x;
    }
    if (lane == 31) wsum[w] = ps;
    __syncthreads();
    if (w == 0) {
        int x = wsum[lane];
        #pragma unroll
        for (int off = 1; off < 32; off <<= 1) {
            int y = __shfl_up_sync(0xffffffffu, x, off);
            if (lane >= off) x += y;
        }
        wsum[lane] = x;
    }
    __syncthreads();
    int excl = ps - s + (w > 0 ? wsum[w - 1] : 0);

    int run = excl;
    #pragma unroll
    for (int u = 0; u < 10; u++) {
        int idx = base + u;
        if (idx < NN) {
            g_csroff[idx] = run;
            g_dinv[idx] = rsqrtf((float)(v[u] + 1));  // +1 self loop
            run += v[u];
        }
    }
    if (t == 1023) g_csroff[NN] = run;
}

// ---------------- scatter edges into CSR (atomic-free), 8/thread ------------
__global__ void fill_kernel(const int* __restrict__ ei) {
    int e8 = (blockIdx.x * blockDim.x + threadIdx.x) * 8;
    if (e8 < EE) {
        int4 sv0 = *(const int4*)(ei + e8);
        int4 sv1 = *(const int4*)(ei + e8 + 4);
        int4 dv0 = *(const int4*)(ei + EE + e8);
        int4 dv1 = *(const int4*)(ei + EE + e8 + 4);
        int4 rv0 = *(const int4*)(g_rank + e8);
        int4 rv1 = *(const int4*)(g_rank + e8 + 4);
        g_csrsrc[g_csroff[dv0.x] + rv0.x] = sv0.x;
        g_csrsrc[g_csroff[dv0.y] + rv0.y] = sv0.y;
        g_csrsrc[g_csroff[dv0.z] + rv0.z] = sv0.z;
        g_csrsrc[g_csroff[dv0.w] + rv0.w] = sv0.w;
        g_csrsrc[g_csroff[dv1.x] + rv1.x] = sv1.x;
        g_csrsrc[g_csroff[dv1.y] + rv1.y] = sv1.y;
        g_csrsrc[g_csroff[dv1.z] + rv1.z] = sv1.z;
        g_csrsrc[g_csroff[dv1.w] + rv1.w] = sv1.w;
    }
}

// ---------------- tf32 tensor-core GEMM body (fp16 output) ------------------
#define GBM 128
#define GBN 128
#define KC  16
#define ASTR 132
#define G1_BLOCKS 158   // 2 col-tiles x 79 row-tiles

__device__ __forceinline__ unsigned f2tf(float x) {
    unsigned r;
    asm("cvt.rna.tf32.f32 %0, %1;" : "=r"(r) : "f"(x));
    return r;
}

__device__ __forceinline__ void mma_tf32(float* d, const unsigned* a, const unsigned* b) {
    asm volatile(
        "mma.sync.aligned.m16n8k8.row.col.f32.tf32.tf32.f32 "
        "{%0,%1,%2,%3}, {%4,%5,%6,%7}, {%8,%9}, {%0,%1,%2,%3};"
        : "+f"(d[0]), "+f"(d[1]), "+f"(d[2]), "+f"(d[3])
        : "r"(a[0]), "r"(a[1]), "r"(a[2]), "r"(a[3]), "r"(b[0]), "r"(b[1]));
}

__device__ __forceinline__ float4 ldA4(const float* __restrict__ A,
                                       int r, int c, int M) {
    if (r < M) return *(const float4*)(A + (long)r * DD + c);
    return make_float4(0.f, 0.f, 0.f, 0.f);
}

__device__ __forceinline__ void gemm_tc_body_h(
    const float* __restrict__ A, const float* __restrict__ B,
    unsigned* __restrict__ Ch, int M, int bx, int by,
    unsigned (*Ah)[KC][ASTR], unsigned (*Bh)[KC][ASTR])
{
    int tid  = threadIdx.x;
    int wid  = tid >> 5, lane = tid & 31;
    int wm   = wid & 3,  wn   = wid >> 2;
    int row0 = by * GBM, col0 = bx * GBN;
    int g = lane >> 2, c = lane & 3;

    int ar = tid >> 2;
    int ac = (tid & 3) << 2;
    int br = tid >> 4;
    int bc = (tid & 15) << 2;

    float acc[2][8][4];
    #pragma unroll
    for (int mf = 0; mf < 2; mf++)
        #pragma unroll
        for (int nf = 0; nf < 8; nf++)
            #pragma unroll
            for (int j = 0; j < 4; j++) acc[mf][nf][j] = 0.f;

    {
        float4 a0 = ldA4(A, row0 + ar,      ac, M);
        float4 a1 = ldA4(A, row0 + ar + 64, ac, M);
        float4 b0 = *(const float4*)(B + (long)br * DD + col0 + bc);
        float4 b1 = *(const float4*)(B + (long)br * DD + col0 + bc + 64);
        float av0[4] = {a0.x, a0.y, a0.z, a0.w};
        float av1[4] = {a1.x, a1.y, a1.z, a1.w};
        #pragma unroll
        for (int i = 0; i < 4; i++) {
            Ah[0][ac + i][ar]      = f2tf(av0[i]);
            Ah[0][ac + i][ar + 64] = f2tf(av1[i]);
        }
        uint4 p0 = make_uint4(f2tf(b0.x), f2tf(b0.y), f2tf(b0.z), f2tf(b0.w));
        uint4 p1 = make_uint4(f2tf(b1.x), f2tf(b1.y), f2tf(b1.z), f2tf(b1.w));
        *(uint4*)&Bh[0][br][bc]      = p0;
        *(uint4*)&Bh[0][br][bc + 64] = p1;
    }
    __syncthreads();

    #pragma unroll 1
    for (int kt = 0; kt < DD / KC; kt++) {
        int buf = kt & 1;
        float4 na0, na1, nb0, nb1;
        if (kt < DD / KC - 1) {
            int k0 = (kt + 1) * KC;
            na0 = ldA4(A, row0 + ar,      k0 + ac, M);
            na1 = ldA4(A, row0 + ar + 64, k0 + ac, M);
            nb0 = *(const float4*)(B + (long)(k0 + br) * DD + col0 + bc);
            nb1 = *(const float4*)(B + (long)(k0 + br) * DD + col0 + bc + 64);
        }
        #pragma unroll
        for (int k8 = 0; k8 < KC / 8; k8++) {
            unsigned ah[2][4], bh[8][2];
            #pragma unroll
            for (int mf = 0; mf < 2; mf++)
                #pragma unroll
                for (int j = 0; j < 4; j++) {
                    int rr = wm * 32 + mf * 16 + g + 8 * (j & 1);
                    int kk = k8 * 8 + c + 4 * (j >> 1);
                    ah[mf][j] = Ah[buf][kk][rr];
                }
            #pragma unroll
            for (int nf = 0; nf < 8; nf++)
                #pragma unroll
                for (int j = 0; j < 2; j++) {
                    int kk = k8 * 8 + c + 4 * j;
                    int nn = wn * 64 + nf * 8 + g;
                    bh[nf][j] = Bh[buf][kk][nn];
                }
            #pragma unroll
            for (int mf = 0; mf < 2; mf++)
                #pragma unroll
                for (int nf = 0; nf < 8; nf++)
                    mma_tf32(acc[mf][nf], ah[mf], bh[nf]);
        }
        if (kt < DD / KC - 1) {
            int nb = buf ^ 1;
            float av0[4] = {na0.x, na0.y, na0.z, na0.w};
            float av1[4] = {na1.x, na1.y, na1.z, na1.w};
            #pragma unroll
            for (int i = 0; i < 4; i++) {
                Ah[nb][ac + i][ar]      = f2tf(av0[i]);
                Ah[nb][ac + i][ar + 64] = f2tf(av1[i]);
            }
            uint4 p0 = make_uint4(f2tf(nb0.x), f2tf(nb0.y), f2tf(nb0.z), f2tf(nb0.w));
            uint4 p1 = make_uint4(f2tf(nb1.x), f2tf(nb1.y), f2tf(nb1.z), f2tf(nb1.w));
            *(uint4*)&Bh[nb][br][bc]      = p0;
            *(uint4*)&Bh[nb][br][bc + 64] = p1;
            __syncthreads();
        }
    }

    // epilogue: store as half2 words (col pairs 2c,2c+1 are adjacent)
    #pragma unroll
    for (int mf = 0; mf < 2; mf++)
        #pragma unroll
        for (int j2 = 0; j2 < 2; j2++) {
            int gr = row0 + wm * 32 + mf * 16 + g + 8 * j2;
            if (gr < M) {
                #pragma unroll
                for (int nf = 0; nf < 8; nf++) {
                    __half2 h = __float22half2_rn(
                        make_float2(acc[mf][nf][j2 * 2], acc[mf][nf][j2 * 2 + 1]));
                    int pc = (col0 >> 1) + wn * 32 + nf * 4 + c;
                    Ch[(long)gr * DH + pc] = *(unsigned*)&h;
                }
            }
        }
}

// ---------------- fused: gemm1 (blocks 0..157) + count (blocks 158..314) ----
__global__ void __launch_bounds__(256) fused_g1_count_kernel(
    const float* __restrict__ A, const float* __restrict__ B,
    const int* __restrict__ ei)
{
    __shared__ unsigned Ahs[2][KC][ASTR];
    __shared__ unsigned Bhs[2][KC][ASTR];
    if (blockIdx.x < G1_BLOCKS) {
        gemm_tc_body_h(A, B, g_xw1h, NN, blockIdx.x & 1, blockIdx.x >> 1, Ahs, Bhs);
    } else {
        int e8 = ((blockIdx.x - G1_BLOCKS) * 256 + threadIdx.x) * 8;
        if (e8 < EE) {
            int4 d0 = *(const int4*)(ei + EE + e8);
            int4 d1 = *(const int4*)(ei + EE + e8 + 4);
            int4 r0, r1;
            r0.x = atomicAdd(&g_indeg[d0.x], 1);
            r0.y = atomicAdd(&g_indeg[d0.y], 1);
            r0.z = atomicAdd(&g_indeg[d0.z], 1);
            r0.w = atomicAdd(&g_indeg[d0.w], 1);
            r1.x = atomicAdd(&g_indeg[d1.x], 1);
            r1.y = atomicAdd(&g_indeg[d1.y], 1);
            r1.z = atomicAdd(&g_indeg[d1.z], 1);
            r1.w = atomicAdd(&g_indeg[d1.w], 1);
            *(int4*)(g_rank + e8)     = r0;
            *(int4*)(g_rank + e8 + 4) = r1;
        }
    }
}

__global__ void __launch_bounds__(256) gemm2_kernel(const float* __restrict__ B) {
    __shared__ unsigned Ahs[2][KC][ASTR];
    __shared__ unsigned Bhs[2][KC][ASTR];
    gemm_tc_body_h(g_x1, B, g_xw2h, NN, blockIdx.x, blockIdx.y, Ahs, Bhs);
}

// ---------------- GCN aggregation: warp per node, fp16 gather ---------------
__global__ void __launch_bounds__(128) gcn_agg_kernel(const float* __restrict__ b1) {
    int lane = threadIdx.x & 31;
    int i = blockIdx.x * 4 + (threadIdx.x >> 5);
    if (i >= NN) return;

    const uint4* xwh = (const uint4*)g_xw1h;
    float di = g_dinv[i];
    float a[8] = {0.f, 0.f, 0.f, 0.f, 0.f, 0.f, 0.f, 0.f};

    acc8(xwh[(long)i * DU + lane], di * di, a);     // self loop

    int beg = g_csroff[i], end = g_csroff[i + 1];
    for (int e0 = beg; e0 < end; e0 += 32) {
        int cnt = end - e0; if (cnt > 32) cnt = 32;
        int jl = (e0 + lane < end) ? g_csrsrc[e0 + lane] : 0;
        float wl = di * g_dinv[jl];
        #pragma unroll 8
        for (int k = 0; k < cnt; k++) {
            int j    = __shfl_sync(0xffffffffu, jl, k);
            float ww = __shfl_sync(0xffffffffu, wl, k);
            acc8(xwh[(long)j * DU + lane], ww, a);
        }
    }
    // bias + relu
    float4 bb0 = ((const float4*)b1)[lane * 2];
    float4 bb1 = ((const float4*)b1)[lane * 2 + 1];
    a[0] = fmaxf(a[0] + bb0.x, 0.f); a[1] = fmaxf(a[1] + bb0.y, 0.f);
    a[2] = fmaxf(a[2] + bb0.z, 0.f); a[3] = fmaxf(a[3] + bb0.w, 0.f);
    a[4] = fmaxf(a[4] + bb1.x, 0.f); a[5] = fmaxf(a[5] + bb1.y, 0.f);
    a[6] = fmaxf(a[6] + bb1.z, 0.f); a[7] = fmaxf(a[7] + bb1.w, 0.f);

    float4* x1v = (float4*)g_x1;
    x1v[(long)i * D4 + lane * 2]     = make_float4(a[0], a[1], a[2], a[3]);
    x1v[(long)i * D4 + lane * 2 + 1] = make_float4(a[4], a[5], a[6], a[7]);

    // fused attention dots
    float4 va0 = ((const float4*)g_va)[lane * 2];
    float4 va1 = ((const float4*)g_va)[lane * 2 + 1];
    float4 vd0 = ((const float4*)g_vd)[lane * 2];
    float4 vd1 = ((const float4*)g_vd)[lane * 2 + 1];
    float ds = a[0]*va0.x + a[1]*va0.y + a[2]*va0.z + a[3]*va0.w
             + a[4]*va1.x + a[5]*va1.y + a[6]*va1.z + a[7]*va1.w;
    float dd = a[0]*vd0.x + a[1]*vd0.y + a[2]*vd0.z + a[3]*vd0.w
             + a[4]*vd1.x + a[5]*vd1.y + a[6]*vd1.z + a[7]*vd1.w;
    #pragma unroll
    for (int off = 16; off; off >>= 1) {
        ds += __shfl_down_sync(0xffffffffu, ds, off);
        dd += __shfl_down_sync(0xffffffffu, dd, off);
    }
    if (lane == 0) { g_as[i] = ds; g_ad[i] = dd; }
}

// ---------------- GAT aggregation: warp per node, online softmax ------------
__global__ void __launch_bounds__(128) gat_agg_kernel(const float* __restrict__ b2,
                                                      float* __restrict__ out) {
    int lane = threadIdx.x & 31;
    int i = blockIdx.x * 4 + (threadIdx.x >> 5);
    if (i >= NN) return;

    float adi = g_ad[i];
    int beg = g_csroff[i], end = g_csroff[i + 1];
    float e_self = lrelu02(g_as[i] + adi);

    // online softmax (lane-strided), bfly merge -> all lanes hold (m, s)
    float lm = -1e30f, ls = 0.f;
    for (int e = beg + lane; e < end; e += 32) {
        float ev = lrelu02(g_as[g_csrsrc[e]] + adi);
        if (ev > lm) { ls = ls * __expf(lm - ev) + 1.f; lm = ev; }
        else         { ls += __expf(ev - lm); }
    }
    #pragma unroll
    for (int off = 16; off; off >>= 1) {
        float m2 = __shfl_xor_sync(0xffffffffu, lm, off);
        float s2 = __shfl_xor_sync(0xffffffffu, ls, off);
        float M = fmaxf(lm, m2);
        ls = ls * __expf(lm - M) + s2 * __expf(m2 - M);
        lm = M;
    }
    float m = fmaxf(lm, e_self);
    float ssum = ls * __expf(lm - m) + __expf(e_self - m);
    float inv = 1.f / (ssum + 1e-16f);

    const uint4* xwh = (const uint4*)g_xw2h;
    float a[8] = {0.f, 0.f, 0.f, 0.f, 0.f, 0.f, 0.f, 0.f};
    acc8(xwh[(long)i * DU + lane], __expf(e_self - m) * inv, a);   // self

    for (int e0 = beg; e0 < end; e0 += 32) {
        int cnt = end - e0; if (cnt > 32) cnt = 32;
        int jl = (e0 + lane < end) ? g_csrsrc[e0 + lane] : 0;
        float wl = __expf(lrelu02(g_as[jl] + adi) - m) * inv;
        #pragma unroll 8
        for (int k = 0; k < cnt; k++) {
            int j    = __shfl_sync(0xffffffffu, jl, k);
            float ww = __shfl_sync(0xffffffffu, wl, k);
            acc8(xwh[(long)j * DU + lane], ww, a);
        }
    }
    float4 bb0 = ((const float4*)b2)[lane * 2];
    float4 bb1 = ((const float4*)b2)[lane * 2 + 1];
    a[0] = fmaxf(a[0] + bb0.x, 0.f); a[1] = fmaxf(a[1] + bb0.y, 0.f);
    a[2] = fmaxf(a[2] + bb0.z, 0.f); a[3] = fmaxf(a[3] + bb0.w, 0.f);
    a[4] = fmaxf(a[4] + bb1.x, 0.f); a[5] = fmaxf(a[5] + bb1.y, 0.f);
    a[6] = fmaxf(a[6] + bb1.z, 0.f); a[7] = fmaxf(a[7] + bb1.w, 0.f);

    float4* ov = (float4*)out;
    ov[(long)i * D4 + lane * 2]     = make_float4(a[0], a[1], a[2], a[3]);
    ov[(long)i * D4 + lane * 2 + 1] = make_float4(a[4], a[5], a[6], a[7]);
}

// ---------------- launch ----------------------------------------------------
extern "C" void kernel_launch(void* const* d_in, const int* in_sizes, int n_in,
                              void* d_out, int out_size) {
    const float* event_emb = (const float*)d_in[0];
    const int*   edge_idx  = (const int*)  d_in[1];
    const float* W1        = (const float*)d_in[2];
    const float* b1        = (const float*)d_in[3];
    const float* W2        = (const float*)d_in[4];
    const float* att_src   = (const float*)d_in[5];
    const float* att_dst   = (const float*)d_in[6];
    const float* b2        = (const float*)d_in[7];
    float* out = (float*)d_out;

    prep_kernel<<<40, 256>>>(W2, att_src, att_dst);
    fused_g1_count_kernel<<<G1_BLOCKS + 157, 256>>>(event_emb, W1, edge_idx);
    scan_kernel<<<1, 1024>>>();
    fill_kernel<<<157, 256>>>(edge_idx);

    gcn_agg_kernel<<<NN / 4, 128>>>(b1);
    dim3 ggrid(DD / GBN, (NN + GBM - 1) / GBM);   // (2, 79)
    gemm2_kernel<<<ggrid, 256>>>(W2);
    gat_agg_kernel<<<NN / 4, 128>>>(b2, out);
}